// round 13
// baseline (speedup 1.0000x reference)
#include <cuda_runtime.h>

// out[b,k] = tanh( sum_n W[k,n] * x[b,k,n] )
// B=64, K=4096, N=256 (fp32). One warp per (b,k) output row.
//
// R1 body, 512-thread CTAs — the one launch-shape axis never varied.
// 16384 CTAs x 16 warps (vs 32768 x 8): halves wave count (221 -> 110) and
// coarsens the bid->smid interleave of the x stream. Per the B300 model the
// chip byte cap is path-independent so this should land inside the
// established noise band (42.4-43.7us over 5 replications of the 256-thread
// form); this is a zero-risk confirmation probe since best-so-far is kept.

#define GK 4096
#define GN 256

__global__ __launch_bounds__(512, 4)
void ginn_input_kernel512(const float* __restrict__ x,
                          const float* __restrict__ W,
                          float* __restrict__ out,
                          int total_outputs) {
    int warp = (blockIdx.x * blockDim.x + threadIdx.x) >> 5;
    int lane = threadIdx.x & 31;
    if (warp >= total_outputs) return;

    int k = warp & (GK - 1);  // K = 4096 (power of 2)

    const float4* __restrict__ xp =
        reinterpret_cast<const float4*>(x + (size_t)warp * GN);
    const float4* __restrict__ wp =
        reinterpret_cast<const float4*>(W + (size_t)k * GN);

    // 256 floats = 64 float4; 32 lanes * 2, all 4 loads front-batched.
    float4 x0 = xp[lane];
    float4 w0 = wp[lane];
    float4 x1 = xp[lane + 32];
    float4 w1 = wp[lane + 32];

    float s = x0.x * w0.x;
    s = fmaf(x0.y, w0.y, s);
    s = fmaf(x0.z, w0.z, s);
    s = fmaf(x0.w, w0.w, s);
    s = fmaf(x1.x, w1.x, s);
    s = fmaf(x1.y, w1.y, s);
    s = fmaf(x1.z, w1.z, s);
    s = fmaf(x1.w, w1.w, s);

    // butterfly reduce across the warp
    #pragma unroll
    for (int off = 16; off > 0; off >>= 1)
        s += __shfl_xor_sync(0xffffffffu, s, off);

    if (lane == 0)
        out[warp] = tanhf(s);
}

extern "C" void kernel_launch(void* const* d_in, const int* in_sizes, int n_in,
                              void* d_out, int out_size) {
    const float* x = (const float*)d_in[0];  // [B, K, N] fp32
    const float* W = (const float*)d_in[1];  // [K, N] fp32
    float* out = (float*)d_out;              // [B, K] fp32

    const int total_outputs = out_size;      // B*K = 262144
    const int threads = 512;                 // 16 warps/block -> 16 outputs/block
    const int warps_per_block = threads / 32;
    const int blocks = (total_outputs + warps_per_block - 1) / warps_per_block;

    ginn_input_kernel512<<<blocks, threads>>>(x, W, out, total_outputs);
}

// round 14
// speedup vs baseline: 1.0522x; 1.0522x over previous
#include <cuda_runtime.h>

// out[b,k] = tanh( sum_n W[k,n] * x[b,k,n] )
// B=64, K=4096, N=256 (fp32). One warp per (b,k) output row.
//
// FINAL — roofline-optimal at the achieved-HBM wall.
// Thirteen rounds of evidence, nine structures, five replications.
// Compulsory traffic: 268 MB x + 4 MB W + 1 MB out = 276 MB, moved at
// 6.3-6.55 TB/s (79-82.6% of 8 TB/s spec) by every correct variant:
//   2-row MLP-deep (R2), W-in-registers halving L2 traffic (R3), contiguous
//   per-SM streams (R4), .cs/.ldg hints + exact grid (R5), half-warp
//   4-level reduce (R8), 512-thread CTAs (R13, slightly worse) — all within
//   or below the +/-0.6us replication noise band (R7/R9/R10/R11/R12).
// Adjudicated real effects: loop-carried load dependencies regress 2.6x
// (R6 persistent pipeline); everything else is non-binding. One fresh
// dependency-free warp per row lets the CTA scheduler saturate the
// chip-wide LDG queue for free — 221 waves of zero-dependency loads.

#define GK 4096
#define GN 256

__global__ __launch_bounds__(256, 8)
void ginn_input_kernel(const float* __restrict__ x,
                       const float* __restrict__ W,
                       float* __restrict__ out,
                       int total_outputs) {
    int warp = (blockIdx.x * blockDim.x + threadIdx.x) >> 5;
    int lane = threadIdx.x & 31;
    if (warp >= total_outputs) return;

    int k = warp & (GK - 1);  // K = 4096 (power of 2)

    const float4* __restrict__ xp =
        reinterpret_cast<const float4*>(x + (size_t)warp * GN);
    const float4* __restrict__ wp =
        reinterpret_cast<const float4*>(W + (size_t)k * GN);

    // 256 floats = 64 float4; 32 lanes * 2, all 4 loads front-batched.
    float4 x0 = xp[lane];
    float4 w0 = wp[lane];
    float4 x1 = xp[lane + 32];
    float4 w1 = wp[lane + 32];

    float s = x0.x * w0.x;
    s = fmaf(x0.y, w0.y, s);
    s = fmaf(x0.z, w0.z, s);
    s = fmaf(x0.w, w0.w, s);
    s = fmaf(x1.x, w1.x, s);
    s = fmaf(x1.y, w1.y, s);
    s = fmaf(x1.z, w1.z, s);
    s = fmaf(x1.w, w1.w, s);

    // butterfly reduce across the warp
    #pragma unroll
    for (int off = 16; off > 0; off >>= 1)
        s += __shfl_xor_sync(0xffffffffu, s, off);

    if (lane == 0)
        out[warp] = tanhf(s);
}

extern "C" void kernel_launch(void* const* d_in, const int* in_sizes, int n_in,
                              void* d_out, int out_size) {
    const float* x = (const float*)d_in[0];  // [B, K, N] fp32
    const float* W = (const float*)d_in[1];  // [K, N] fp32
    float* out = (float*)d_out;              // [B, K] fp32

    const int total_outputs = out_size;      // B*K = 262144
    const int threads = 256;                 // 8 warps/block -> 8 outputs/block
    const int warps_per_block = threads / 32;
    const int blocks = (total_outputs + warps_per_block - 1) / warps_per_block;

    ginn_input_kernel<<<blocks, threads>>>(x, W, out, total_outputs);
}

// round 15
// speedup vs baseline: 1.0530x; 1.0007x over previous
#include <cuda_runtime.h>

// out[b,k] = tanh( sum_n W[k,n] * x[b,k,n] )
// B=64, K=4096, N=256 (fp32). One warp per (b,k) output row.
//
// FINAL — roofline-optimal at the achieved-HBM wall.
// Fourteen rounds: nine structures tried, six replications of this source
// (bench 43.46-43.78us, ncu 42.4-43.7us, DRAM 79.4-82.6%). Compulsory
// traffic: 268 MB x + 4 MB W + 1 MB out = 276 MB at 6.3-6.55 TB/s — the
// measured pattern-independent achieved-HBM ceiling of this part.
// Closed axes: warp/row mapping, MLP depth (R2), W-in-registers / L2
// traffic halving (R3), per-SM stream contiguity + TLB (R4), cache & store
// policies (R5), reduce depth / instruction count (R8), CTA shape (R13),
// software pipelining (R6: loop-carried load deps -> 2.6x regression, the
// session's only non-noise effect). TMA ruled out analytically (same
// path-independent chip byte cap as LDG). One fresh dependency-free warp
// per row lets the CTA scheduler saturate the chip-wide LDG queue for free.

#define GK 4096
#define GN 256

__global__ __launch_bounds__(256, 8)
void ginn_input_kernel(const float* __restrict__ x,
                       const float* __restrict__ W,
                       float* __restrict__ out,
                       int total_outputs) {
    int warp = (blockIdx.x * blockDim.x + threadIdx.x) >> 5;
    int lane = threadIdx.x & 31;
    if (warp >= total_outputs) return;

    int k = warp & (GK - 1);  // K = 4096 (power of 2)

    const float4* __restrict__ xp =
        reinterpret_cast<const float4*>(x + (size_t)warp * GN);
    const float4* __restrict__ wp =
        reinterpret_cast<const float4*>(W + (size_t)k * GN);

    // 256 floats = 64 float4; 32 lanes * 2, all 4 loads front-batched.
    float4 x0 = xp[lane];
    float4 w0 = wp[lane];
    float4 x1 = xp[lane + 32];
    float4 w1 = wp[lane + 32];

    float s = x0.x * w0.x;
    s = fmaf(x0.y, w0.y, s);
    s = fmaf(x0.z, w0.z, s);
    s = fmaf(x0.w, w0.w, s);
    s = fmaf(x1.x, w1.x, s);
    s = fmaf(x1.y, w1.y, s);
    s = fmaf(x1.z, w1.z, s);
    s = fmaf(x1.w, w1.w, s);

    // butterfly reduce across the warp
    #pragma unroll
    for (int off = 16; off > 0; off >>= 1)
        s += __shfl_xor_sync(0xffffffffu, s, off);

    if (lane == 0)
        out[warp] = tanhf(s);
}

extern "C" void kernel_launch(void* const* d_in, const int* in_sizes, int n_in,
                              void* d_out, int out_size) {
    const float* x = (const float*)d_in[0];  // [B, K, N] fp32
    const float* W = (const float*)d_in[1];  // [K, N] fp32
    float* out = (float*)d_out;              // [B, K] fp32

    const int total_outputs = out_size;      // B*K = 262144
    const int threads = 256;                 // 8 warps/block -> 8 outputs/block
    const int warps_per_block = threads / 32;
    const int blocks = (total_outputs + warps_per_block - 1) / warps_per_block;

    ginn_input_kernel<<<blocks, threads>>>(x, W, out, total_outputs);
}